// round 1
// baseline (speedup 1.0000x reference)
#include <cuda_runtime.h>
#include <cstdint>
#include <cstddef>

// Problem constants (fixed by the dataset: B=4, S=4096, H=16, D=64)
#define BSZ 4
#define SEQ 4096
#define NH 16
#define HD 64
#define CK 128               // chunk length
#define NC (SEQ / CK)        // 32 chunks
#define BH (BSZ * NH)        // 64 (b,h) pairs
#define ROWSTRIDE (NH * HD)  // 1024 floats between consecutive s for same (b,h)

// Scratch: per-chunk KV outer products, later overwritten in-place with the
// EXCLUSIVE prefix sum. [BH][NC][HD][HD] = 64*32*64*64 floats = 32 MB.
__device__ float g_kv[(size_t)BH * NC * HD * HD];

// ---------------------------------------------------------------------------
// Kernel 1: per-chunk KV_n[d][e] = sum_{j<CK} k[j][d] * v[j][e]
// grid = BH*NC (2048), block = 256. Thread tile 4x4 with stride-16 interleave.
// ---------------------------------------------------------------------------
__global__ __launch_bounds__(256, 1) void kv_chunk_kernel(
    const float* __restrict__ kg, const float* __restrict__ vg) {
    const int blk = blockIdx.x;
    const int n  = blk % NC;
    const int bh = blk / NC;
    const int h  = bh % NH;
    const int b  = bh / NH;

    __shared__ float ks[64][64];
    __shared__ float vs[64][64];

    const int tid = threadIdx.x;
    const int tx = tid & 15;   // e-group
    const int ty = tid >> 4;   // d-group

    float acc[4][4];
#pragma unroll
    for (int r = 0; r < 4; r++)
#pragma unroll
        for (int c = 0; c < 4; c++) acc[r][c] = 0.f;

    const size_t base = ((size_t)b * SEQ + (size_t)n * CK) * ROWSTRIDE + (size_t)h * HD;

    for (int half = 0; half < 2; half++) {
        __syncthreads();
        // load 64 rows x 64 cols of k and v (coalesced)
        for (int t = tid; t < 64 * 64; t += 256) {
            const int j = t >> 6, d = t & 63;
            const size_t g = base + (size_t)(half * 64 + j) * ROWSTRIDE + d;
            ks[j][d] = kg[g];
            vs[j][d] = vg[g];
        }
        __syncthreads();
#pragma unroll 4
        for (int j = 0; j < 64; j++) {
            float kr[4], vr[4];
#pragma unroll
            for (int r = 0; r < 4; r++) kr[r] = ks[j][ty + 16 * r];
#pragma unroll
            for (int c = 0; c < 4; c++) vr[c] = vs[j][tx + 16 * c];
#pragma unroll
            for (int r = 0; r < 4; r++)
#pragma unroll
                for (int c = 0; c < 4; c++)
                    acc[r][c] = fmaf(kr[r], vr[c], acc[r][c]);
        }
    }

    float* out = g_kv + ((size_t)bh * NC + n) * (HD * HD);
#pragma unroll
    for (int r = 0; r < 4; r++)
#pragma unroll
        for (int c = 0; c < 4; c++)
            out[(ty + 16 * r) * HD + (tx + 16 * c)] = acc[r][c];
}

// ---------------------------------------------------------------------------
// Kernel 2: in-place EXCLUSIVE prefix over the chunk axis, per (bh, d, e).
// grid = BH*16 (1024), block = 256: one thread per (d,e) element of one bh.
// Consecutive threads -> consecutive e: fully coalesced strided walk.
// ---------------------------------------------------------------------------
__global__ __launch_bounds__(256, 1) void kv_prefix_kernel() {
    const int bh  = blockIdx.x >> 4;
    const int off = ((blockIdx.x & 15) << 8) + threadIdx.x;  // 0..4095
    float* p = g_kv + (size_t)bh * NC * (HD * HD) + off;
    float run = 0.f;
#pragma unroll
    for (int n = 0; n < NC; n++) {
        const float t = p[(size_t)n * (HD * HD)];
        p[(size_t)n * (HD * HD)] = run;
        run += t;
    }
}

// ---------------------------------------------------------------------------
// Kernel 3: per chunk, O = tril(Q K^T) V + Q KV_prev
// grid = BH*NC (2048), block = 256, dynamic smem ~176 KB.
// Phase 1: S[i][j] (8x8/thread, stride-16 interleave; K transposed in smem
//          with stride 129 so both the transpose-write and the per-d read are
//          bank-conflict-free; Q reads are warp broadcasts from row-major).
// Phase 2: O[i][e] (8x4/thread): S reads are broadcasts, V/KV reads hit 16
//          distinct banks.
// ---------------------------------------------------------------------------
__global__ __launch_bounds__(256, 1) void out_kernel(
    const float* __restrict__ qg, const float* __restrict__ kg,
    const float* __restrict__ vg, float* __restrict__ og) {
    extern __shared__ float sm[];
    float* q_s  = sm;                    // [128][64]
    float* v_s  = q_s + CK * HD;         // [128][64]
    float* kT   = v_s + CK * HD;         // [64][129]  (padded transpose)
    float* kv_s = kT + HD * 129;         // [64][64]
    float* Sm   = kv_s + HD * HD;        // [128][128]

    const int blk = blockIdx.x;
    const int n  = blk % NC;
    const int bh = blk / NC;
    const int h  = bh % NH;
    const int b  = bh / NH;

    const int tid = threadIdx.x;
    const int tx = tid & 15;
    const int ty = tid >> 4;

    const size_t base = ((size_t)b * SEQ + (size_t)n * CK) * ROWSTRIDE + (size_t)h * HD;

    // Cooperative loads (coalesced global; kT write is conflict-free: bank =
    // (129*d + i) % 32 = (d + i) % 32 with d consecutive across lanes).
    for (int t = tid; t < CK * HD; t += 256) {
        const int i = t >> 6, d = t & 63;
        const size_t g = base + (size_t)i * ROWSTRIDE + d;
        q_s[t] = qg[g];
        v_s[t] = vg[g];
        kT[d * 129 + i] = kg[g];
    }
    const float* kvp = g_kv + ((size_t)bh * NC + n) * (HD * HD);
    for (int t = tid; t < HD * HD; t += 256) kv_s[t] = kvp[t];
    __syncthreads();

    // ---- Phase 1: S = mask(Q K^T), 8x8 per thread -------------------------
    {
        float sacc[8][8];
#pragma unroll
        for (int r = 0; r < 8; r++)
#pragma unroll
            for (int c = 0; c < 8; c++) sacc[r][c] = 0.f;

#pragma unroll 2
        for (int d = 0; d < HD; d++) {
            float qr[8], kr[8];
#pragma unroll
            for (int r = 0; r < 8; r++) qr[r] = q_s[(ty + 16 * r) * HD + d];
#pragma unroll
            for (int c = 0; c < 8; c++) kr[c] = kT[d * 129 + (tx + 16 * c)];
#pragma unroll
            for (int r = 0; r < 8; r++)
#pragma unroll
                for (int c = 0; c < 8; c++)
                    sacc[r][c] = fmaf(qr[r], kr[c], sacc[r][c]);
        }
        // masked write (j <= i causal, diagonal included)
#pragma unroll
        for (int r = 0; r < 8; r++) {
            const int i = ty + 16 * r;
#pragma unroll
            for (int c = 0; c < 8; c++) {
                const int j = tx + 16 * c;
                Sm[i * CK + j] = (j <= i) ? sacc[r][c] : 0.f;
            }
        }
    }
    __syncthreads();

    // ---- Phase 2: O = S V + Q KV_prev, 8x4 per thread ---------------------
    {
        float oacc[8][4];
#pragma unroll
        for (int r = 0; r < 8; r++)
#pragma unroll
            for (int c = 0; c < 4; c++) oacc[r][c] = 0.f;

        // inter-chunk term: sum_d q[i][d] * kv_prev[d][e]
#pragma unroll 2
        for (int d = 0; d < HD; d++) {
            float qr[8], kvr[4];
#pragma unroll
            for (int r = 0; r < 8; r++) qr[r] = q_s[(ty + 16 * r) * HD + d];
#pragma unroll
            for (int c = 0; c < 4; c++) kvr[c] = kv_s[d * HD + (tx + 16 * c)];
#pragma unroll
            for (int r = 0; r < 8; r++)
#pragma unroll
                for (int c = 0; c < 4; c++)
                    oacc[r][c] = fmaf(qr[r], kvr[c], oacc[r][c]);
        }
        // intra-chunk term: sum_j S[i][j] * v[j][e]
#pragma unroll 2
        for (int j = 0; j < CK; j++) {
            float sr[8], vr[4];
#pragma unroll
            for (int r = 0; r < 8; r++) sr[r] = Sm[(ty + 16 * r) * CK + j];
#pragma unroll
            for (int c = 0; c < 4; c++) vr[c] = v_s[j * HD + (tx + 16 * c)];
#pragma unroll
            for (int r = 0; r < 8; r++)
#pragma unroll
                for (int c = 0; c < 4; c++)
                    oacc[r][c] = fmaf(sr[r], vr[c], oacc[r][c]);
        }

#pragma unroll
        for (int r = 0; r < 8; r++) {
            const int i = ty + 16 * r;
#pragma unroll
            for (int c = 0; c < 4; c++) {
                const int e = tx + 16 * c;
                og[base + (size_t)i * ROWSTRIDE + e] = oacc[r][c];
            }
        }
    }
}

// ---------------------------------------------------------------------------
// kernel_launch: 3 launches, all graph-capturable (no sync, no alloc).
// Inputs per metadata order: q, k, v (float32), attn_mask (unused).
// ---------------------------------------------------------------------------
extern "C" void kernel_launch(void* const* d_in, const int* in_sizes, int n_in,
                              void* d_out, int out_size) {
    (void)in_sizes; (void)n_in; (void)out_size;
    const float* q = (const float*)d_in[0];
    const float* k = (const float*)d_in[1];
    const float* v = (const float*)d_in[2];
    float* out = (float*)d_out;

    kv_chunk_kernel<<<BH * NC, 256>>>(k, v);
    kv_prefix_kernel<<<BH * 16, 256>>>();

    const int smem_bytes =
        (CK * HD + CK * HD + HD * 129 + HD * HD + CK * CK) * (int)sizeof(float);  // 180480
    cudaFuncSetAttribute(out_kernel, cudaFuncAttributeMaxDynamicSharedMemorySize,
                         smem_bytes);
    out_kernel<<<BH * NC, 256, smem_bytes>>>(q, k, v, out);
}

// round 3
// speedup vs baseline: 1.9146x; 1.9146x over previous
#include <cuda_runtime.h>
#include <cuda_bf16.h>
#include <cstdint>
#include <cstddef>

// Problem constants (B=4, S=4096, H=16, D=64)
#define BSZ 4
#define SEQ 4096
#define NH 16
#define HD 64
#define CK 128
#define NC 32
#define BH 64
#define ROWSTRIDE 1024

// Per-chunk KV outer products -> exclusive prefix (in place). 32 MB.
__device__ float g_kv[(size_t)BH * NC * HD * HD];

// ---------------------------------------------------------------------------
// smem geometry for the mma out-kernel (byte offsets; bf16 elements)
//   Q2  [128][200]  rows i, cols k (0-63 QH, 64-127 QH, 128-191 QL)
//   K2  [128][200]  rows j, cols k (KH, KL, KH)
//   KVT [ 64][200]  rows e, cols d (KVT_H, KVT_L, KVT_H)
//   VT  [ 64][392]  rows e, cols j (VT_H, VT_L, VT_H)
//   S2  [128][392]  rows i, cols j (SH, SH, SL)  -- overlays Q2+K2 after S
// Row strides 200/392 bf16 = 400/784 B  =>  mod 128 B = 16 => ldmatrix
// row-rotation hits all 8 bank-quads: conflict-free.
// ---------------------------------------------------------------------------
#define LDQ 200
#define LDSBIG 392
#define Q2_OFF 0
#define K2_OFF 51200
#define KVT_OFF 102400
#define VT_OFF 128000
#define S2_OFF 0
#define SMEM_TOTAL (VT_OFF + 64 * LDSBIG * 2)   // 178176 bytes

// ---------------------------------------------------------------------------
// PTX helpers (base sm_100-safe: ldmatrix + mma.sync only)
// ---------------------------------------------------------------------------
__device__ __forceinline__ uint32_t smem_u32(const void* p) {
    uint32_t a;
    asm("{ .reg .u64 t; cvta.to.shared.u64 t, %1; cvt.u32.u64 %0, t; }"
        : "=r"(a) : "l"(p));
    return a;
}
__device__ __forceinline__ void ldmA(uint32_t* r, uint32_t addr) {
    asm volatile("ldmatrix.sync.aligned.m8n8.x4.shared.b16 {%0,%1,%2,%3}, [%4];"
                 : "=r"(r[0]), "=r"(r[1]), "=r"(r[2]), "=r"(r[3]) : "r"(addr));
}
__device__ __forceinline__ void ldmB(uint32_t* r, uint32_t addr) {
    asm volatile("ldmatrix.sync.aligned.m8n8.x2.shared.b16 {%0,%1}, [%2];"
                 : "=r"(r[0]), "=r"(r[1]) : "r"(addr));
}
__device__ __forceinline__ void mma16816(float* c, const uint32_t* a, const uint32_t* b) {
    asm volatile(
        "mma.sync.aligned.m16n8k16.row.col.f32.bf16.bf16.f32 "
        "{%0,%1,%2,%3}, {%4,%5,%6,%7}, {%8,%9}, {%0,%1,%2,%3};"
        : "+f"(c[0]), "+f"(c[1]), "+f"(c[2]), "+f"(c[3])
        : "r"(a[0]), "r"(a[1]), "r"(a[2]), "r"(a[3]), "r"(b[0]), "r"(b[1]));
}

// split fp32 -> (hi, lo) bf16
__device__ __forceinline__ void split1(float x, __nv_bfloat16& h, __nv_bfloat16& l) {
    h = __float2bfloat16(x);
    l = __float2bfloat16(x - __bfloat162float(h));
}
// split fp32 pair -> packed bf16x2 hi and lo
__device__ __forceinline__ void split2(float x0, float x1, uint32_t& hi, uint32_t& lo) {
    __nv_bfloat16 h0, l0, h1, l1;
    split1(x0, h0, l0);
    split1(x1, h1, l1);
    hi = (uint32_t)__bfloat16_as_ushort(h0) | ((uint32_t)__bfloat16_as_ushort(h1) << 16);
    lo = (uint32_t)__bfloat16_as_ushort(l0) | ((uint32_t)__bfloat16_as_ushort(l1) << 16);
}

// ---------------------------------------------------------------------------
// Kernel 1: per-chunk KV_n[d][e] = sum_j k[j][d] * v[j][e]  (unchanged)
// ---------------------------------------------------------------------------
__global__ __launch_bounds__(256, 1) void kv_chunk_kernel(
    const float* __restrict__ kg, const float* __restrict__ vg) {
    const int blk = blockIdx.x;
    const int n  = blk % NC;
    const int bh = blk / NC;
    const int h  = bh % NH;
    const int b  = bh / NH;

    __shared__ float ks[64][64];
    __shared__ float vs[64][64];

    const int tid = threadIdx.x;
    const int tx = tid & 15;
    const int ty = tid >> 4;

    float acc[4][4];
#pragma unroll
    for (int r = 0; r < 4; r++)
#pragma unroll
        for (int c = 0; c < 4; c++) acc[r][c] = 0.f;

    const size_t base = ((size_t)b * SEQ + (size_t)n * CK) * ROWSTRIDE + (size_t)h * HD;

    for (int half = 0; half < 2; half++) {
        __syncthreads();
        for (int t = tid; t < 64 * 64; t += 256) {
            const int j = t >> 6, d = t & 63;
            const size_t g = base + (size_t)(half * 64 + j) * ROWSTRIDE + d;
            ks[j][d] = kg[g];
            vs[j][d] = vg[g];
        }
        __syncthreads();
#pragma unroll 4
        for (int j = 0; j < 64; j++) {
            float kr[4], vr[4];
#pragma unroll
            for (int r = 0; r < 4; r++) kr[r] = ks[j][ty + 16 * r];
#pragma unroll
            for (int c = 0; c < 4; c++) vr[c] = vs[j][tx + 16 * c];
#pragma unroll
            for (int r = 0; r < 4; r++)
#pragma unroll
                for (int c = 0; c < 4; c++)
                    acc[r][c] = fmaf(kr[r], vr[c], acc[r][c]);
        }
    }

    float* out = g_kv + ((size_t)bh * NC + n) * (HD * HD);
#pragma unroll
    for (int r = 0; r < 4; r++)
#pragma unroll
        for (int c = 0; c < 4; c++)
            out[(ty + 16 * r) * HD + (tx + 16 * c)] = acc[r][c];
}

// ---------------------------------------------------------------------------
// Kernel 2: in-place exclusive prefix over chunk axis (unchanged)
// ---------------------------------------------------------------------------
__global__ __launch_bounds__(256, 1) void kv_prefix_kernel() {
    const int bh  = blockIdx.x >> 4;
    const int off = ((blockIdx.x & 15) << 8) + threadIdx.x;
    float* p = g_kv + (size_t)bh * NC * (HD * HD) + off;
    float run = 0.f;
#pragma unroll
    for (int n = 0; n < NC; n++) {
        const float t = p[(size_t)n * (HD * HD)];
        p[(size_t)n * (HD * HD)] = run;
        run += t;
    }
}

// ---------------------------------------------------------------------------
// Kernel 3: mma.sync bf16-split out kernel.
//   O = Q KV_prev + tril(Q K^T) V    per chunk of 128 rows.
// grid = 2048, block = 256 (8 warps), smem 174 KB, 1 CTA/SM.
// Warp tiling: S (128x128): 4x2 warps, 32x64/warp.
//              O (128x64):  4x2 warps, 32x32/warp.
// K-concat split: A'=[QH|QH|QL] etc. (see smem geometry above).
// ---------------------------------------------------------------------------
__global__ __launch_bounds__(256, 1) void out_mma_kernel(
    const float* __restrict__ qg, const float* __restrict__ kg,
    const float* __restrict__ vg, float* __restrict__ og) {
    extern __shared__ char sm[];
    const uint32_t smb = smem_u32(sm);

    const int tid = threadIdx.x, wid = tid >> 5, lane = tid & 31;
    const int blk = blockIdx.x;
    const int n = blk & (NC - 1), bh = blk >> 5;
    const int h = bh & (NH - 1), b = bh >> 4;
    const size_t base = ((size_t)b * SEQ + (size_t)n * CK) * ROWSTRIDE + (size_t)h * HD;

    // ---- load + fp32->bf16 hi/lo convert -------------------------------
    {
        uint32_t* q2u = (uint32_t*)(sm + Q2_OFF);
        uint32_t* k2u = (uint32_t*)(sm + K2_OFF);
#pragma unroll
        for (int p = tid; p < 4096; p += 256) {
            const int i = p >> 5, dp = p & 31;
            const size_t g = base + (size_t)i * ROWSTRIDE + 2 * dp;
            float2 xq = *(const float2*)(qg + g);
            float2 xk = *(const float2*)(kg + g);
            uint32_t qh, ql, kh, kl;
            split2(xq.x, xq.y, qh, ql);
            split2(xk.x, xk.y, kh, kl);
            const int r = i * (LDQ / 2);
            q2u[r + dp] = qh;  q2u[r + 32 + dp] = qh;  q2u[r + 64 + dp] = ql;
            k2u[r + dp] = kh;  k2u[r + 32 + dp] = kl;  k2u[r + 64 + dp] = kh;
        }
        __nv_bfloat16* vt = (__nv_bfloat16*)(sm + VT_OFF);
#pragma unroll
        for (int p = tid; p < 8192; p += 256) {
            const int j = p >> 6, e = p & 63;
            const float x = vg[base + (size_t)j * ROWSTRIDE + e];
            __nv_bfloat16 hh, ll;
            split1(x, hh, ll);
            const int r = e * LDSBIG;
            vt[r + j] = hh;  vt[r + 256 + j] = hh;  vt[r + 128 + j] = ll;
        }
        const float* kvsrc = g_kv + ((size_t)bh * NC + n) * (HD * HD);
        __nv_bfloat16* kvt = (__nv_bfloat16*)(sm + KVT_OFF);
#pragma unroll
        for (int p = tid; p < 4096; p += 256) {
            const int d = p >> 6, e = p & 63;
            const float x = kvsrc[d * 64 + e];
            __nv_bfloat16 hh, ll;
            split1(x, hh, ll);
            const int r = e * LDQ;
            kvt[r + d] = hh;  kvt[r + 128 + d] = hh;  kvt[r + 64 + d] = ll;
        }
    }
    __syncthreads();

    // ---- warp/lane ldmatrix geometry -----------------------------------
    const int wr  = wid & 3;   // i block (32 rows)
    const int wc  = wid >> 2;  // S: j block of 64; O: e block of 32
    const int la15 = lane & 15;
    const int la7  = lane & 7;
    const int aCol = (lane >> 4) << 3;         // 0 or 8
    const int bCol = ((lane >> 3) & 1) << 3;   // 0 or 8

    uint32_t aQ[2], bKV[4], bK[8];
#pragma unroll
    for (int f = 0; f < 2; f++)
        aQ[f] = smb + Q2_OFF + 2 * ((wr * 32 + f * 16 + la15) * LDQ + aCol);
#pragma unroll
    for (int g = 0; g < 4; g++)
        bKV[g] = smb + KVT_OFF + 2 * ((wc * 32 + g * 8 + la7) * LDQ + bCol);
#pragma unroll
    for (int g = 0; g < 8; g++)
        bK[g] = smb + K2_OFF + 2 * ((wc * 64 + g * 8 + la7) * LDQ + bCol);

    // ---- O_inter = Q * KV_prev^T  (K = 192) ----------------------------
    float oacc[2][4][4];
#pragma unroll
    for (int f = 0; f < 2; f++)
#pragma unroll
        for (int g = 0; g < 4; g++)
#pragma unroll
            for (int c = 0; c < 4; c++) oacc[f][g][c] = 0.f;

#pragma unroll 2
    for (int kb = 0; kb < 12; kb++) {
        uint32_t a[2][4];
        ldmA(a[0], aQ[0] + kb * 32);
        ldmA(a[1], aQ[1] + kb * 32);
#pragma unroll
        for (int g = 0; g < 4; g++) {
            uint32_t bb[2];
            ldmB(bb, bKV[g] + kb * 32);
            mma16816(oacc[0][g], a[0], bb);
            mma16816(oacc[1][g], a[1], bb);
        }
    }

    // ---- S = Q * K^T  (K = 192) ----------------------------------------
    float sacc[2][8][4];
#pragma unroll
    for (int f = 0; f < 2; f++)
#pragma unroll
        for (int g = 0; g < 8; g++)
#pragma unroll
            for (int c = 0; c < 4; c++) sacc[f][g][c] = 0.f;

#pragma unroll 2
    for (int kb = 0; kb < 12; kb++) {
        uint32_t a[2][4];
        ldmA(a[0], aQ[0] + kb * 32);
        ldmA(a[1], aQ[1] + kb * 32);
#pragma unroll
        for (int g = 0; g < 8; g++) {
            uint32_t bb[2];
            ldmB(bb, bK[g] + kb * 32);
            mma16816(sacc[0][g], a[0], bb);
            mma16816(sacc[1][g], a[1], bb);
        }
    }
    __syncthreads();   // everyone done reading Q2/K2

    // ---- mask + split S -> S2 [SH|SH|SL] (overlays Q2/K2) --------------
    {
        uint32_t* s2u = (uint32_t*)(sm + S2_OFF);
        const int gid = lane >> 2, t4 = lane & 3;
#pragma unroll
        for (int f = 0; f < 2; f++) {
#pragma unroll
            for (int g = 0; g < 8; g++) {
                const int j0 = wc * 64 + g * 8 + 2 * t4;
#pragma unroll
                for (int half = 0; half < 2; half++) {
                    const int i = wr * 32 + f * 16 + gid + half * 8;
                    const float x0 = (j0     <= i) ? sacc[f][g][2 * half]     : 0.f;
                    const float x1 = (j0 + 1 <= i) ? sacc[f][g][2 * half + 1] : 0.f;
                    uint32_t hi, lo;
                    split2(x0, x1, hi, lo);
                    const int r = i * (LDSBIG / 2) + (j0 >> 1);
                    s2u[r] = hi;  s2u[r + 64] = hi;  s2u[r + 128] = lo;
                }
            }
        }
    }
    __syncthreads();

    // ---- O_intra = S * V^T  (K = 384) ----------------------------------
    uint32_t aS[2], bVT[4];
#pragma unroll
    for (int f = 0; f < 2; f++)
        aS[f] = smb + S2_OFF + 2 * ((wr * 32 + f * 16 + la15) * LDSBIG + aCol);
#pragma unroll
    for (int g = 0; g < 4; g++)
        bVT[g] = smb + VT_OFF + 2 * ((wc * 32 + g * 8 + la7) * LDSBIG + bCol);

#pragma unroll 2
    for (int kb = 0; kb < 24; kb++) {
        uint32_t a[2][4];
        ldmA(a[0], aS[0] + kb * 32);
        ldmA(a[1], aS[1] + kb * 32);
#pragma unroll
        for (int g = 0; g < 4; g++) {
            uint32_t bb[2];
            ldmB(bb, bVT[g] + kb * 32);
            mma16816(oacc[0][g], a[0], bb);
            mma16816(oacc[1][g], a[1], bb);
        }
    }

    // ---- epilogue: write O ---------------------------------------------
    {
        const int gid = lane >> 2, t4 = lane & 3;
#pragma unroll
        for (int f = 0; f < 2; f++) {
#pragma unroll
            for (int g = 0; g < 4; g++) {
                const int e0 = wc * 32 + g * 8 + 2 * t4;
#pragma unroll
                for (int half = 0; half < 2; half++) {
                    const int i = wr * 32 + f * 16 + gid + half * 8;
                    float2 v2 = make_float2(oacc[f][g][2 * half], oacc[f][g][2 * half + 1]);
                    *(float2*)(og + base + (size_t)i * ROWSTRIDE + e0) = v2;
                }
            }
        }
    }
}

// ---------------------------------------------------------------------------
// kernel_launch
// ---------------------------------------------------------------------------
extern "C" void kernel_launch(void* const* d_in, const int* in_sizes, int n_in,
                              void* d_out, int out_size) {
    (void)in_sizes; (void)n_in; (void)out_size;
    const float* q = (const float*)d_in[0];
    const float* k = (const float*)d_in[1];
    const float* v = (const float*)d_in[2];
    float* out = (float*)d_out;

    kv_chunk_kernel<<<BH * NC, 256>>>(k, v);
    kv_prefix_kernel<<<BH * 16, 256>>>();

    cudaFuncSetAttribute(out_mma_kernel, cudaFuncAttributeMaxDynamicSharedMemorySize,
                         SMEM_TOTAL);
    out_mma_kernel<<<BH * NC, 256, SMEM_TOTAL>>>(q, k, v, out);
}

// round 4
// speedup vs baseline: 2.5085x; 1.3102x over previous
#include <cuda_runtime.h>
#include <cuda_bf16.h>
#include <cstdint>
#include <cstddef>

// Problem constants (B=4, S=4096, H=16, D=64)
#define BSZ 4
#define SEQ 4096
#define NH 16
#define HD 64
#define CK 128
#define NC 32
#define BH 64
#define ROWSTRIDE 1024

// Per-chunk KV outer products -> exclusive prefix (in place). 32 MB.
__device__ float g_kv[(size_t)BH * NC * HD * HD];

// ---------------------------------------------------------------------------
// PTX helpers (base sm_100-safe)
// ---------------------------------------------------------------------------
__device__ __forceinline__ uint32_t smem_u32(const void* p) {
    uint32_t a;
    asm("{ .reg .u64 t; cvta.to.shared.u64 t, %1; cvt.u32.u64 %0, t; }"
        : "=r"(a) : "l"(p));
    return a;
}
// plain x4 ldmatrix (A row-major frags, or B [n][k] frag pairs)
__device__ __forceinline__ void ldm4(uint32_t* r, uint32_t addr) {
    asm volatile("ldmatrix.sync.aligned.m8n8.x4.shared.b16 {%0,%1,%2,%3}, [%4];"
                 : "=r"(r[0]), "=r"(r[1]), "=r"(r[2]), "=r"(r[3]) : "r"(addr));
}
// x4 trans ldmatrix (operand stored [k][m] / [k][n])
__device__ __forceinline__ void ldm4t(uint32_t* r, uint32_t addr) {
    asm volatile("ldmatrix.sync.aligned.m8n8.x4.trans.shared.b16 {%0,%1,%2,%3}, [%4];"
                 : "=r"(r[0]), "=r"(r[1]), "=r"(r[2]), "=r"(r[3]) : "r"(addr));
}
__device__ __forceinline__ void mma16816(float* c, const uint32_t* a, const uint32_t* b) {
    asm volatile(
        "mma.sync.aligned.m16n8k16.row.col.f32.bf16.bf16.f32 "
        "{%0,%1,%2,%3}, {%4,%5,%6,%7}, {%8,%9}, {%0,%1,%2,%3};"
        : "+f"(c[0]), "+f"(c[1]), "+f"(c[2]), "+f"(c[3])
        : "r"(a[0]), "r"(a[1]), "r"(a[2]), "r"(a[3]), "r"(b[0]), "r"(b[1]));
}

// swizzles: 128B rows ([*][64] bf16) and 256B rows ([*][128] bf16)
__device__ __forceinline__ uint32_t sw128(uint32_t x) { return x ^ ((x >> 3) & 0x70); }
__device__ __forceinline__ uint32_t sw256(uint32_t x) { return x ^ ((x >> 4) & 0x70); }

// split fp32 -> (hi, lo) bf16
__device__ __forceinline__ void split1(float x, __nv_bfloat16& h, __nv_bfloat16& l) {
    h = __float2bfloat16(x);
    l = __float2bfloat16(x - __bfloat162float(h));
}
__device__ __forceinline__ void split2(float x0, float x1, uint32_t& hi, uint32_t& lo) {
    __nv_bfloat16 h0, l0, h1, l1;
    split1(x0, h0, l0);
    split1(x1, h1, l1);
    hi = (uint32_t)__bfloat16_as_ushort(h0) | ((uint32_t)__bfloat16_as_ushort(h1) << 16);
    lo = (uint32_t)__bfloat16_as_ushort(l0) | ((uint32_t)__bfloat16_as_ushort(l1) << 16);
}

// ---------------------------------------------------------------------------
// Kernel 1: per-chunk KV_n[d][e] = sum_j k[j][d] * v[j][e]   (mma.sync version)
// grid = 2048, block = 256 (8 warps), dyn smem 64 KB.
// K,V stored naturally [j:128][64] bf16 hi/lo, SW128; both operands via
// ldmatrix.x4.trans. Warp tile: 16(d) x 32(e); warps wy=wid>>1, wx=wid&1.
// 3 split terms: KH*VH + KH*VL + KL*VH.
// ---------------------------------------------------------------------------
#define KV_KH 0
#define KV_KL 16384
#define KV_VH 32768
#define KV_VL 49152
#define KV_SMEM 65536

__global__ __launch_bounds__(256, 1) void kv_chunk_kernel(
    const float* __restrict__ kg, const float* __restrict__ vg) {
    extern __shared__ char sm[];
    const uint32_t smb = smem_u32(sm);

    const int tid = threadIdx.x, wid = tid >> 5, lane = tid & 31;
    const int blk = blockIdx.x;
    const int n = blk & (NC - 1), bh = blk >> 5;
    const int h = bh & (NH - 1), b = bh >> 4;
    const size_t base = ((size_t)b * SEQ + (size_t)n * CK) * ROWSTRIDE + (size_t)h * HD;

    // load + split: K,V [128][64] -> bf16 hi/lo, natural orientation
#pragma unroll
    for (int p = tid; p < 4096; p += 256) {
        const int j = p >> 5, dp = p & 31;
        const size_t g = base + (size_t)j * ROWSTRIDE + 2 * dp;
        float2 xk = *(const float2*)(kg + g);
        float2 xv = *(const float2*)(vg + g);
        uint32_t kh, kl, vh, vl;
        split2(xk.x, xk.y, kh, kl);
        split2(xv.x, xv.y, vh, vl);
        const uint32_t off = sw128((uint32_t)(j * 128 + dp * 4));
        *(uint32_t*)(sm + KV_KH + off) = kh;
        *(uint32_t*)(sm + KV_KL + off) = kl;
        *(uint32_t*)(sm + KV_VH + off) = vh;
        *(uint32_t*)(sm + KV_VL + off) = vl;
    }
    __syncthreads();

    const int wy = wid >> 1;          // d block of 16
    const int wx = wid & 1;           // e block of 32
    const int la7 = lane & 7;

    float acc[4][4];
#pragma unroll
    for (int f = 0; f < 4; f++)
#pragma unroll
        for (int c = 0; c < 4; c++) acc[f][c] = 0.f;

#pragma unroll 2
    for (int kb = 0; kb < 8; kb++) {
        const int k0 = kb * 16;
        // A = K^T (m=d, k=j), stored [j][d]: trans x4
        // lanes: row j = k0 + ((lane>>4)<<3) + la7, col d = d0 + ((lane>>3)&1)*8
        uint32_t aH[4], aL[4];
        {
            const int row = k0 + ((lane >> 4) << 3) + la7;
            const int col = wy * 16 + ((lane >> 3) & 1) * 8;
            const uint32_t off = sw128((uint32_t)(row * 128 + col * 2));
            ldm4t(aH, smb + KV_KH + off);
            ldm4t(aL, smb + KV_KL + off);
        }
        // B = V^T (n=e, k=j), stored [j][e]: trans x4 -> 2 n8 frags
        // lanes: row j = k0 + ((lane>>3)&1)*8 + la7, col e = e0 + ((lane>>4)<<3)
        uint32_t bH[2][4], bL[2][4];
#pragma unroll
        for (int nb = 0; nb < 2; nb++) {
            const int row = k0 + ((lane >> 3) & 1) * 8 + la7;
            const int col = wx * 32 + nb * 16 + ((lane >> 4) << 3);
            const uint32_t off = sw128((uint32_t)(row * 128 + col * 2));
            ldm4t(bH[nb], smb + KV_VH + off);
            ldm4t(bL[nb], smb + KV_VL + off);
        }
#pragma unroll
        for (int nb = 0; nb < 2; nb++)
#pragma unroll
            for (int f = 0; f < 2; f++) {
                float* c = acc[nb * 2 + f];
                mma16816(c, aH, &bH[nb][2 * f]);
                mma16816(c, aH, &bL[nb][2 * f]);
                mma16816(c, aL, &bH[nb][2 * f]);
            }
    }

    // epilogue: fp32 KV -> g_kv[d][e]
    {
        float* out = g_kv + ((size_t)bh * NC + n) * (HD * HD);
        const int gid = lane >> 2, t4 = lane & 3;
#pragma unroll
        for (int f = 0; f < 4; f++) {
            const int e0 = wx * 32 + f * 8 + 2 * t4;
            const int d0 = wy * 16 + gid;
            *(float2*)(out + d0 * HD + e0) = make_float2(acc[f][0], acc[f][1]);
            *(float2*)(out + (d0 + 8) * HD + e0) = make_float2(acc[f][2], acc[f][3]);
        }
    }
}

// ---------------------------------------------------------------------------
// Kernel 2: in-place exclusive prefix over chunk axis (unchanged)
// ---------------------------------------------------------------------------
__global__ __launch_bounds__(256, 1) void kv_prefix_kernel() {
    const int bh  = blockIdx.x >> 4;
    const int off = ((blockIdx.x & 15) << 8) + threadIdx.x;
    float* p = g_kv + (size_t)bh * NC * (HD * HD) + off;
    float run = 0.f;
#pragma unroll
    for (int n = 0; n < NC; n++) {
        const float t = p[(size_t)n * (HD * HD)];
        p[(size_t)n * (HD * HD)] = run;
        run += t;
    }
}

// ---------------------------------------------------------------------------
// Kernel 3: out kernel, 512 threads, no-dup layout, 112 KB smem.
//   O = Q KV_prev + tril(Q K^T) V per 128-row chunk.
// smem: QH 0, QL 16K, KH 32K, KL 48K   ([128][64] K-major, SW128)
//       KVH 64K, KVL 72K               ([64][64] natural [d][e], SW128)
//       VH 80K, VL 96K                 ([128][64] natural [j][e], SW128)
//       SH 0, SL 32K (overlay Q/K)     ([128][128], SW256)
// Warps: 16; wy=wid>>2 (i block 32), wx=wid&3 (S: j block 32 / O: e block 16).
// ---------------------------------------------------------------------------
#define O_QH 0
#define O_QL 16384
#define O_KH 32768
#define O_KL 49152
#define O_KVH 65536
#define O_KVL 73728
#define O_VH 81920
#define O_VL 98304
#define O_SH 0
#define O_SL 32768
#define O_SMEM 114688

__global__ __launch_bounds__(512, 1) void out_mma_kernel(
    const float* __restrict__ qg, const float* __restrict__ kg,
    const float* __restrict__ vg, float* __restrict__ og) {
    extern __shared__ char sm[];
    const uint32_t smb = smem_u32(sm);

    const int tid = threadIdx.x, wid = tid >> 5, lane = tid & 31;
    const int blk = blockIdx.x;
    const int n = blk & (NC - 1), bh = blk >> 5;
    const int h = bh & (NH - 1), b = bh >> 4;
    const size_t base = ((size_t)b * SEQ + (size_t)n * CK) * ROWSTRIDE + (size_t)h * HD;

    // ---- load + split: Q, K, V (identical addressing) ----
#pragma unroll
    for (int p = tid; p < 4096; p += 512) {
        const int i = p >> 5, dp = p & 31;
        const size_t g = base + (size_t)i * ROWSTRIDE + 2 * dp;
        float2 xq = *(const float2*)(qg + g);
        float2 xk = *(const float2*)(kg + g);
        float2 xv = *(const float2*)(vg + g);
        uint32_t hh, ll;
        const uint32_t off = sw128((uint32_t)(i * 128 + dp * 4));
        split2(xq.x, xq.y, hh, ll);
        *(uint32_t*)(sm + O_QH + off) = hh;
        *(uint32_t*)(sm + O_QL + off) = ll;
        split2(xk.x, xk.y, hh, ll);
        *(uint32_t*)(sm + O_KH + off) = hh;
        *(uint32_t*)(sm + O_KL + off) = ll;
        split2(xv.x, xv.y, hh, ll);
        *(uint32_t*)(sm + O_VH + off) = hh;
        *(uint32_t*)(sm + O_VL + off) = ll;
    }
    // KV_prev [64][64]
    {
        const float* kvsrc = g_kv + ((size_t)bh * NC + n) * (HD * HD);
#pragma unroll
        for (int p = tid; p < 2048; p += 512) {
            const int d = p >> 5, ep = p & 31;
            float2 x = *(const float2*)(kvsrc + d * 64 + 2 * ep);
            uint32_t hh, ll;
            split2(x.x, x.y, hh, ll);
            const uint32_t off = sw128((uint32_t)(d * 128 + ep * 4));
            *(uint32_t*)(sm + O_KVH + off) = hh;
            *(uint32_t*)(sm + O_KVL + off) = ll;
        }
    }
    __syncthreads();

    const int wy = wid >> 2;
    const int wx = wid & 3;
    const int la7 = lane & 7;
    const int la15 = lane & 15;

    float sacc[2][4][4];
    float oacc[2][2][4];
#pragma unroll
    for (int m = 0; m < 2; m++) {
#pragma unroll
        for (int g = 0; g < 4; g++)
#pragma unroll
            for (int c = 0; c < 4; c++) sacc[m][g][c] = 0.f;
#pragma unroll
        for (int g = 0; g < 2; g++)
#pragma unroll
            for (int c = 0; c < 4; c++) oacc[m][g][c] = 0.f;
    }

    // ---- phase A: S = Q K^T (3 terms) and O_inter = Q KV_prev (3 terms) ----
#pragma unroll 1
    for (int kb = 0; kb < 4; kb++) {
        const int k0 = kb * 16;
        uint32_t aH[2][4], aL[2][4];
#pragma unroll
        for (int m = 0; m < 2; m++) {
            const int row = wy * 32 + m * 16 + la15;
            const int col = k0 + ((lane >> 4) << 3);
            const uint32_t off = sw128((uint32_t)(row * 128 + col * 2));
            ldm4(aH[m], smb + O_QH + off);
            ldm4(aL[m], smb + O_QL + off);
        }
        // K as B [n=j][k=d] row-major: plain x4 -> 2 n8 frags
        uint32_t bH[2][4], bL[2][4];
#pragma unroll
        for (int nb = 0; nb < 2; nb++) {
            const int row = wx * 32 + nb * 16 + ((lane >> 4) << 3) + la7;
            const int col = k0 + ((lane >> 3) & 1) * 8;
            const uint32_t off = sw128((uint32_t)(row * 128 + col * 2));
            ldm4(bH[nb], smb + O_KH + off);
            ldm4(bL[nb], smb + O_KL + off);
        }
#pragma unroll
        for (int m = 0; m < 2; m++)
#pragma unroll
            for (int nb = 0; nb < 2; nb++)
#pragma unroll
                for (int f = 0; f < 2; f++) {
                    float* c = sacc[m][nb * 2 + f];
                    mma16816(c, aH[m], &bH[nb][2 * f]);
                    mma16816(c, aH[m], &bL[nb][2 * f]);
                    mma16816(c, aL[m], &bH[nb][2 * f]);
                }
        // KV as B (n=e, k=d), stored [d][e]: trans x4 -> 2 n8 frags
        uint32_t cH[4], cL[4];
        {
            const int row = k0 + ((lane >> 3) & 1) * 8 + la7;
            const int col = wx * 16 + ((lane >> 4) << 3);
            const uint32_t off = sw128((uint32_t)(row * 128 + col * 2));
            ldm4t(cH, smb + O_KVH + off);
            ldm4t(cL, smb + O_KVL + off);
        }
#pragma unroll
        for (int m = 0; m < 2; m++)
#pragma unroll
            for (int f = 0; f < 2; f++) {
                float* c = oacc[m][f];
                mma16816(c, aH[m], &cH[2 * f]);
                mma16816(c, aH[m], &cL[2 * f]);
                mma16816(c, aL[m], &cH[2 * f]);
            }
    }
    __syncthreads();   // all reads of Q/K done before S overlays them

    // ---- phase B: mask + split S -> SH/SL ([128][128], SW256) ----
    {
        const int gid = lane >> 2, t4 = lane & 3;
#pragma unroll
        for (int m = 0; m < 2; m++)
#pragma unroll
            for (int g = 0; g < 4; g++) {
                const int j0 = wx * 32 + g * 8 + 2 * t4;
#pragma unroll
                for (int half = 0; half < 2; half++) {
                    const int i = wy * 32 + m * 16 + gid + half * 8;
                    const float x0 = (j0     <= i) ? sacc[m][g][2 * half]     : 0.f;
                    const float x1 = (j0 + 1 <= i) ? sacc[m][g][2 * half + 1] : 0.f;
                    uint32_t hh, ll;
                    split2(x0, x1, hh, ll);
                    const uint32_t off = sw256((uint32_t)(i * 256 + j0 * 2));
                    *(uint32_t*)(sm + O_SH + off) = hh;
                    *(uint32_t*)(sm + O_SL + off) = ll;
                }
            }
    }
    __syncthreads();

    // ---- phase C: O += S V (3 terms), K = 128 ----
#pragma unroll 1
    for (int kb = 0; kb < 8; kb++) {
        const int k0 = kb * 16;
        uint32_t aH[2][4], aL[2][4];
#pragma unroll
        for (int m = 0; m < 2; m++) {
            const int row = wy * 32 + m * 16 + la15;
            const int col = k0 + ((lane >> 4) << 3);
            const uint32_t off = sw256((uint32_t)(row * 256 + col * 2));
            ldm4(aH[m], smb + O_SH + off);
            ldm4(aL[m], smb + O_SL + off);
        }
        uint32_t bH[4], bL[4];
        {
            const int row = k0 + ((lane >> 3) & 1) * 8 + la7;
            const int col = wx * 16 + ((lane >> 4) << 3);
            const uint32_t off = sw128((uint32_t)(row * 128 + col * 2));
            ldm4t(bH, smb + O_VH + off);
            ldm4t(bL, smb + O_VL + off);
        }
#pragma unroll
        for (int m = 0; m < 2; m++)
#pragma unroll
            for (int f = 0; f < 2; f++) {
                float* c = oacc[m][f];
                mma16816(c, aH[m], &bH[2 * f]);
                mma16816(c, aH[m], &bL[2 * f]);
                mma16816(c, aL[m], &bH[2 * f]);
            }
    }

    // ---- epilogue ----
    {
        const int gid = lane >> 2, t4 = lane & 3;
#pragma unroll
        for (int m = 0; m < 2; m++)
#pragma unroll
            for (int f = 0; f < 2; f++) {
                const int e0 = wx * 16 + f * 8 + 2 * t4;
                const int i0 = wy * 32 + m * 16 + gid;
                *(float2*)(og + base + (size_t)i0 * ROWSTRIDE + e0) =
                    make_float2(oacc[m][f][0], oacc[m][f][1]);
                *(float2*)(og + base + (size_t)(i0 + 8) * ROWSTRIDE + e0) =
                    make_float2(oacc[m][f][2], oacc[m][f][3]);
            }
    }
}

// ---------------------------------------------------------------------------
// kernel_launch
// ---------------------------------------------------------------------------
extern "C" void kernel_launch(void* const* d_in, const int* in_sizes, int n_in,
                              void* d_out, int out_size) {
    (void)in_sizes; (void)n_in; (void)out_size;
    const float* q = (const float*)d_in[0];
    const float* k = (const float*)d_in[1];
    const float* v = (const float*)d_in[2];
    float* out = (float*)d_out;

    cudaFuncSetAttribute(kv_chunk_kernel, cudaFuncAttributeMaxDynamicSharedMemorySize,
                         KV_SMEM);
    kv_chunk_kernel<<<BH * NC, 256, KV_SMEM>>>(k, v);
    kv_prefix_kernel<<<BH * 16, 256>>>();

    cudaFuncSetAttribute(out_mma_kernel, cudaFuncAttributeMaxDynamicSharedMemorySize,
                         O_SMEM);
    out_mma_kernel<<<BH * NC, 512, O_SMEM>>>(q, k, v, out);
}

// round 5
// speedup vs baseline: 2.7600x; 1.1003x over previous
#include <cuda_runtime.h>
#include <cuda_bf16.h>
#include <cstdint>
#include <cstddef>

// Problem constants (B=4, S=4096, H=16, D=64)
#define BSZ 4
#define SEQ 4096
#define NH 16
#define HD 64
#define CK 128
#define NC 32
#define BH 64
#define ROWSTRIDE 1024

// Per-chunk KV outer products -> exclusive prefix (in place). 32 MB.
__device__ float g_kv[(size_t)BH * NC * HD * HD];

// ---------------------------------------------------------------------------
// PTX helpers (base sm_100-safe)
// ---------------------------------------------------------------------------
__device__ __forceinline__ uint32_t smem_u32(const void* p) {
    uint32_t a;
    asm("{ .reg .u64 t; cvta.to.shared.u64 t, %1; cvt.u32.u64 %0, t; }"
        : "=r"(a) : "l"(p));
    return a;
}
__device__ __forceinline__ void ldm4(uint32_t* r, uint32_t addr) {
    asm volatile("ldmatrix.sync.aligned.m8n8.x4.shared.b16 {%0,%1,%2,%3}, [%4];"
                 : "=r"(r[0]), "=r"(r[1]), "=r"(r[2]), "=r"(r[3]) : "r"(addr));
}
__device__ __forceinline__ void ldm4t(uint32_t* r, uint32_t addr) {
    asm volatile("ldmatrix.sync.aligned.m8n8.x4.trans.shared.b16 {%0,%1,%2,%3}, [%4];"
                 : "=r"(r[0]), "=r"(r[1]), "=r"(r[2]), "=r"(r[3]) : "r"(addr));
}
__device__ __forceinline__ void mma16816(float* c, const uint32_t* a, const uint32_t* b) {
    asm volatile(
        "mma.sync.aligned.m16n8k16.row.col.f32.bf16.bf16.f32 "
        "{%0,%1,%2,%3}, {%4,%5,%6,%7}, {%8,%9}, {%0,%1,%2,%3};"
        : "+f"(c[0]), "+f"(c[1]), "+f"(c[2]), "+f"(c[3])
        : "r"(a[0]), "r"(a[1]), "r"(a[2]), "r"(a[3]), "r"(b[0]), "r"(b[1]));
}

// swizzles: 128B rows ([*][64] bf16) and 256B rows ([*][128] bf16)
__device__ __forceinline__ uint32_t sw128(uint32_t x) { return x ^ ((x >> 3) & 0x70); }
__device__ __forceinline__ uint32_t sw256(uint32_t x) { return x ^ ((x >> 4) & 0x70); }

// split fp32 -> (hi, lo) bf16
__device__ __forceinline__ void split1(float x, __nv_bfloat16& h, __nv_bfloat16& l) {
    h = __float2bfloat16(x);
    l = __float2bfloat16(x - __bfloat162float(h));
}
__device__ __forceinline__ void split2(float x0, float x1, uint32_t& hi, uint32_t& lo) {
    __nv_bfloat16 h0, l0, h1, l1;
    split1(x0, h0, l0);
    split1(x1, h1, l1);
    hi = (uint32_t)__bfloat16_as_ushort(h0) | ((uint32_t)__bfloat16_as_ushort(h1) << 16);
    lo = (uint32_t)__bfloat16_as_ushort(l0) | ((uint32_t)__bfloat16_as_ushort(l1) << 16);
}

// ---------------------------------------------------------------------------
// Kernel 1: per-chunk KV_n[d][e] = sum_j k[j][d] * v[j][e]
// grid = 2048, block = 512 (16 warps), smem 64 KB, 2 CTAs/SM.
// Warp tile 16(d) x 16(e): wy=wid>>2, wx=wid&3. 3 split terms.
// ---------------------------------------------------------------------------
#define KV_KH 0
#define KV_KL 16384
#define KV_VH 32768
#define KV_VL 49152
#define KV_SMEM 65536

__global__ __launch_bounds__(512, 2) void kv_chunk_kernel(
    const float* __restrict__ kg, const float* __restrict__ vg) {
    extern __shared__ char sm[];
    const uint32_t smb = smem_u32(sm);

    const int tid = threadIdx.x, wid = tid >> 5, lane = tid & 31;
    const int blk = blockIdx.x;
    const int n = blk & (NC - 1), bh = blk >> 5;
    const int h = bh & (NH - 1), b = bh >> 4;
    const size_t base = ((size_t)b * SEQ + (size_t)n * CK) * ROWSTRIDE + (size_t)h * HD;

    // load + split: K,V [128][64] -> bf16 hi/lo, natural orientation
#pragma unroll
    for (int p = tid; p < 4096; p += 512) {
        const int j = p >> 5, dp = p & 31;
        const size_t g = base + (size_t)j * ROWSTRIDE + 2 * dp;
        float2 xk = *(const float2*)(kg + g);
        float2 xv = *(const float2*)(vg + g);
        uint32_t kh, kl, vh, vl;
        split2(xk.x, xk.y, kh, kl);
        split2(xv.x, xv.y, vh, vl);
        const uint32_t off = sw128((uint32_t)(j * 128 + dp * 4));
        *(uint32_t*)(sm + KV_KH + off) = kh;
        *(uint32_t*)(sm + KV_KL + off) = kl;
        *(uint32_t*)(sm + KV_VH + off) = vh;
        *(uint32_t*)(sm + KV_VL + off) = vl;
    }
    __syncthreads();

    const int wy = wid >> 2;          // d block of 16
    const int wx = wid & 3;           // e block of 16
    const int la7 = lane & 7;

    float acc[2][4];
#pragma unroll
    for (int f = 0; f < 2; f++)
#pragma unroll
        for (int c = 0; c < 4; c++) acc[f][c] = 0.f;

#pragma unroll 2
    for (int kb = 0; kb < 8; kb++) {
        const int k0 = kb * 16;
        // A = K^T (m=d, k=j), stored [j][d]: trans x4
        uint32_t aH[4], aL[4];
        {
            const int row = k0 + ((lane >> 4) << 3) + la7;
            const int col = wy * 16 + ((lane >> 3) & 1) * 8;
            const uint32_t off = sw128((uint32_t)(row * 128 + col * 2));
            ldm4t(aH, smb + KV_KH + off);
            ldm4t(aL, smb + KV_KL + off);
        }
        // B = V^T (n=e, k=j), stored [j][e]: trans x4 -> 2 n8 frags
        uint32_t bH[4], bL[4];
        {
            const int row = k0 + ((lane >> 3) & 1) * 8 + la7;
            const int col = wx * 16 + ((lane >> 4) << 3);
            const uint32_t off = sw128((uint32_t)(row * 128 + col * 2));
            ldm4t(bH, smb + KV_VH + off);
            ldm4t(bL, smb + KV_VL + off);
        }
#pragma unroll
        for (int f = 0; f < 2; f++) {
            float* c = acc[f];
            mma16816(c, aH, &bH[2 * f]);
            mma16816(c, aH, &bL[2 * f]);
            mma16816(c, aL, &bH[2 * f]);
        }
    }

    // epilogue: fp32 KV -> g_kv[d][e]
    {
        float* out = g_kv + ((size_t)bh * NC + n) * (HD * HD);
        const int gid = lane >> 2, t4 = lane & 3;
#pragma unroll
        for (int f = 0; f < 2; f++) {
            const int e0 = wx * 16 + f * 8 + 2 * t4;
            const int d0 = wy * 16 + gid;
            *(float2*)(out + d0 * HD + e0) = make_float2(acc[f][0], acc[f][1]);
            *(float2*)(out + (d0 + 8) * HD + e0) = make_float2(acc[f][2], acc[f][3]);
        }
    }
}

// ---------------------------------------------------------------------------
// Kernel 2: in-place exclusive prefix over chunk axis (unchanged)
// ---------------------------------------------------------------------------
__global__ __launch_bounds__(256, 1) void kv_prefix_kernel() {
    const int bh  = blockIdx.x >> 4;
    const int off = ((blockIdx.x & 15) << 8) + threadIdx.x;
    float* p = g_kv + (size_t)bh * NC * (HD * HD) + off;
    float run = 0.f;
#pragma unroll
    for (int n = 0; n < NC; n++) {
        const float t = p[(size_t)n * (HD * HD)];
        p[(size_t)n * (HD * HD)] = run;
        run += t;
    }
}

// ---------------------------------------------------------------------------
// Kernel 3: out kernel, O = [S | Q] · [V ; KV_prev] with S = tril(Q K^T).
// grid = 2048, block = 512 (16 warps), smem 144 KB, 1 CTA/SM.
// smem: QH 0, QL 16K          ([128][64] K-major, SW128)  -- live all phases
//       KH 32K, KL 48K        ([128][64] K-major, SW128)  -- dead after A
//       SH 32K, SL 64K        ([128][128], SW256)  SH overlays KH+KL
//       KVH 96K, KVL 104K     ([64][64] natural [d][e], SW128)
//       VH 112K, VL 128K      ([128][64] natural [j][e], SW128)
// Phase A: S = Q K^T (sacc only, 32 floats).
// Phase B: mask+split S.
// Phase C: O = S·V + Q·KV (oacc only, 16 floats), 12 k-blocks.
// ---------------------------------------------------------------------------
#define O_QH 0
#define O_QL 16384
#define O_KH 32768
#define O_KL 49152
#define O_SH 32768
#define O_SL 65536
#define O_KVH 98304
#define O_KVL 106496
#define O_VH 114688
#define O_VL 131072
#define O_SMEM 147456

__global__ __launch_bounds__(512, 1) void out_mma_kernel(
    const float* __restrict__ qg, const float* __restrict__ kg,
    const float* __restrict__ vg, float* __restrict__ og) {
    extern __shared__ char sm[];
    const uint32_t smb = smem_u32(sm);

    const int tid = threadIdx.x, wid = tid >> 5, lane = tid & 31;
    const int blk = blockIdx.x;
    const int n = blk & (NC - 1), bh = blk >> 5;
    const int h = bh & (NH - 1), b = bh >> 4;
    const size_t base = ((size_t)b * SEQ + (size_t)n * CK) * ROWSTRIDE + (size_t)h * HD;

    // ---- load + split: Q, K, V ----
#pragma unroll
    for (int p = tid; p < 4096; p += 512) {
        const int i = p >> 5, dp = p & 31;
        const size_t g = base + (size_t)i * ROWSTRIDE + 2 * dp;
        float2 xq = *(const float2*)(qg + g);
        float2 xk = *(const float2*)(kg + g);
        float2 xv = *(const float2*)(vg + g);
        uint32_t hh, ll;
        const uint32_t off = sw128((uint32_t)(i * 128 + dp * 4));
        split2(xq.x, xq.y, hh, ll);
        *(uint32_t*)(sm + O_QH + off) = hh;
        *(uint32_t*)(sm + O_QL + off) = ll;
        split2(xk.x, xk.y, hh, ll);
        *(uint32_t*)(sm + O_KH + off) = hh;
        *(uint32_t*)(sm + O_KL + off) = ll;
        split2(xv.x, xv.y, hh, ll);
        *(uint32_t*)(sm + O_VH + off) = hh;
        *(uint32_t*)(sm + O_VL + off) = ll;
    }
    // KV_prev [64][64]
    {
        const float* kvsrc = g_kv + ((size_t)bh * NC + n) * (HD * HD);
#pragma unroll
        for (int p = tid; p < 2048; p += 512) {
            const int d = p >> 5, ep = p & 31;
            float2 x = *(const float2*)(kvsrc + d * 64 + 2 * ep);
            uint32_t hh, ll;
            split2(x.x, x.y, hh, ll);
            const uint32_t off = sw128((uint32_t)(d * 128 + ep * 4));
            *(uint32_t*)(sm + O_KVH + off) = hh;
            *(uint32_t*)(sm + O_KVL + off) = ll;
        }
    }
    __syncthreads();

    const int wy = wid >> 2;   // i block of 32
    const int wx = wid & 3;    // S: j block of 32 / O: e block of 16
    const int la7 = lane & 7;
    const int la15 = lane & 15;

    // ---- phase A: S = Q K^T (3 split terms) ----
    float sacc[2][4][4];
#pragma unroll
    for (int m = 0; m < 2; m++)
#pragma unroll
        for (int g = 0; g < 4; g++)
#pragma unroll
            for (int c = 0; c < 4; c++) sacc[m][g][c] = 0.f;

#pragma unroll 2
    for (int kb = 0; kb < 4; kb++) {
        const int k0 = kb * 16;
        uint32_t aH[2][4], aL[2][4];
#pragma unroll
        for (int m = 0; m < 2; m++) {
            const int row = wy * 32 + m * 16 + la15;
            const int col = k0 + ((lane >> 4) << 3);
            const uint32_t off = sw128((uint32_t)(row * 128 + col * 2));
            ldm4(aH[m], smb + O_QH + off);
            ldm4(aL[m], smb + O_QL + off);
        }
        uint32_t bH[2][4], bL[2][4];
#pragma unroll
        for (int nb = 0; nb < 2; nb++) {
            const int row = wx * 32 + nb * 16 + ((lane >> 4) << 3) + la7;
            const int col = k0 + ((lane >> 3) & 1) * 8;
            const uint32_t off = sw128((uint32_t)(row * 128 + col * 2));
            ldm4(bH[nb], smb + O_KH + off);
            ldm4(bL[nb], smb + O_KL + off);
        }
#pragma unroll
        for (int m = 0; m < 2; m++)
#pragma unroll
            for (int nb = 0; nb < 2; nb++)
#pragma unroll
                for (int f = 0; f < 2; f++) {
                    float* c = sacc[m][nb * 2 + f];
                    mma16816(c, aH[m], &bH[nb][2 * f]);
                    mma16816(c, aH[m], &bL[nb][2 * f]);
                    mma16816(c, aL[m], &bH[nb][2 * f]);
                }
    }
    __syncthreads();   // all reads of K done before S overlays it

    // ---- phase B: mask + split S -> SH/SL ([128][128], SW256) ----
    {
        const int gid = lane >> 2, t4 = lane & 3;
#pragma unroll
        for (int m = 0; m < 2; m++)
#pragma unroll
            for (int g = 0; g < 4; g++) {
                const int j0 = wx * 32 + g * 8 + 2 * t4;
#pragma unroll
                for (int half = 0; half < 2; half++) {
                    const int i = wy * 32 + m * 16 + gid + half * 8;
                    const float x0 = (j0     <= i) ? sacc[m][g][2 * half]     : 0.f;
                    const float x1 = (j0 + 1 <= i) ? sacc[m][g][2 * half + 1] : 0.f;
                    uint32_t hh, ll;
                    split2(x0, x1, hh, ll);
                    const uint32_t off = sw256((uint32_t)(i * 256 + j0 * 2));
                    *(uint32_t*)(sm + O_SH + off) = hh;
                    *(uint32_t*)(sm + O_SL + off) = ll;
                }
            }
    }
    __syncthreads();

    // ---- phase C: O = S·V + Q·KV (3 split terms each) ----
    float oacc[2][2][4];
#pragma unroll
    for (int m = 0; m < 2; m++)
#pragma unroll
        for (int f = 0; f < 2; f++)
#pragma unroll
            for (int c = 0; c < 4; c++) oacc[m][f][c] = 0.f;

    // sub-loop 1: A = S (k = j, 8 blocks), B = V
#pragma unroll 2
    for (int kb = 0; kb < 8; kb++) {
        const int k0 = kb * 16;
        uint32_t aH[2][4], aL[2][4];
#pragma unroll
        for (int m = 0; m < 2; m++) {
            const int row = wy * 32 + m * 16 + la15;
            const int col = k0 + ((lane >> 4) << 3);
            const uint32_t off = sw256((uint32_t)(row * 256 + col * 2));
            ldm4(aH[m], smb + O_SH + off);
            ldm4(aL[m], smb + O_SL + off);
        }
        uint32_t bH[4], bL[4];
        {
            const int row = k0 + ((lane >> 3) & 1) * 8 + la7;
            const int col = wx * 16 + ((lane >> 4) << 3);
            const uint32_t off = sw128((uint32_t)(row * 128 + col * 2));
            ldm4t(bH, smb + O_VH + off);
            ldm4t(bL, smb + O_VL + off);
        }
#pragma unroll
        for (int m = 0; m < 2; m++)
#pragma unroll
            for (int f = 0; f < 2; f++) {
                float* c = oacc[m][f];
                mma16816(c, aH[m], &bH[2 * f]);
                mma16816(c, aH[m], &bL[2 * f]);
                mma16816(c, aL[m], &bH[2 * f]);
            }
    }
    // sub-loop 2: A = Q (k = d, 4 blocks), B = KV_prev
#pragma unroll 2
    for (int kb = 0; kb < 4; kb++) {
        const int k0 = kb * 16;
        uint32_t aH[2][4], aL[2][4];
#pragma unroll
        for (int m = 0; m < 2; m++) {
            const int row = wy * 32 + m * 16 + la15;
            const int col = k0 + ((lane >> 4) << 3);
            const uint32_t off = sw128((uint32_t)(row * 128 + col * 2));
            ldm4(aH[m], smb + O_QH + off);
            ldm4(aL[m], smb + O_QL + off);
        }
        uint32_t bH[4], bL[4];
        {
            const int row = k0 + ((lane >> 3) & 1) * 8 + la7;
            const int col = wx * 16 + ((lane >> 4) << 3);
            const uint32_t off = sw128((uint32_t)(row * 128 + col * 2));
            ldm4t(bH, smb + O_KVH + off);
            ldm4t(bL, smb + O_KVL + off);
        }
#pragma unroll
        for (int m = 0; m < 2; m++)
#pragma unroll
            for (int f = 0; f < 2; f++) {
                float* c = oacc[m][f];
                mma16816(c, aH[m], &bH[2 * f]);
                mma16816(c, aH[m], &bL[2 * f]);
                mma16816(c, aL[m], &bH[2 * f]);
            }
    }

    // ---- epilogue ----
    {
        const int gid = lane >> 2, t4 = lane & 3;
#pragma unroll
        for (int m = 0; m < 2; m++)
#pragma unroll
            for (int f = 0; f < 2; f++) {
                const int e0 = wx * 16 + f * 8 + 2 * t4;
                const int i0 = wy * 32 + m * 16 + gid;
                *(float2*)(og + base + (size_t)i0 * ROWSTRIDE + e0) =
                    make_float2(oacc[m][f][0], oacc[m][f][1]);
                *(float2*)(og + base + (size_t)(i0 + 8) * ROWSTRIDE + e0) =
                    make_float2(oacc[m][f][2], oacc[m][f][3]);
            }
    }
}

// ---------------------------------------------------------------------------
// kernel_launch
// ---------------------------------------------------------------------------
extern "C" void kernel_launch(void* const* d_in, const int* in_sizes, int n_in,
                              void* d_out, int out_size) {
    (void)in_sizes; (void)n_in; (void)out_size;
    const float* q = (const float*)d_in[0];
    const float* k = (const float*)d_in[1];
    const float* v = (const float*)d_in[2];
    float* out = (float*)d_out;

    cudaFuncSetAttribute(kv_chunk_kernel, cudaFuncAttributeMaxDynamicSharedMemorySize,
                         KV_SMEM);
    kv_chunk_kernel<<<BH * NC, 512, KV_SMEM>>>(k, v);
    kv_prefix_kernel<<<BH * 16, 256>>>();

    cudaFuncSetAttribute(out_mma_kernel, cudaFuncAttributeMaxDynamicSharedMemorySize,
                         O_SMEM);
    out_mma_kernel<<<BH * NC, 512, O_SMEM>>>(q, k, v, out);
}